// round 9
// baseline (speedup 1.0000x reference)
#include <cuda_runtime.h>
#include <cuda_bf16.h>

// y = x @ (A@B)^T + bias  ==  T = x@B^T (32x64);  y = T@A^T + bias
// Fused persistent kernel: 128 blocks x 512 threads.
// - XOR-swizzled conflict-free smem tiles
// - 2r x 2b register blocking, packed f32x2 FMA
// - T accumulated via red.global.add.v2.f32 in TWO WAVES overlapped with
//   phase-1 compute (barrier #1 arrive at kernel start, wait mid-phase)
// - tight-poll grid barriers

#define BATCH 32
#define IN_F  8192
#define OUT_F 8192
#define RANK  64
#define GRID  128
#define TPB   512
#define S1_CHUNK 64
#define OTILE    64

__device__ float        g_T[BATCH * RANK];
__device__ unsigned int g_bar;   // monotonic ticket counter; never reset

#define FMA2(acc, a, b) \
    asm("fma.rn.f32x2 %0, %1, %2, %0;" : "+l"(acc) : "l"(a), "l"(b))
#define ADD2(d, a, b) \
    asm("add.rn.f32x2 %0, %1, %2;" : "=l"(d) : "l"(a), "l"(b))

__device__ __forceinline__ float hsum2(unsigned long long v) {
    float lo, hi;
    asm("mov.b64 {%0, %1}, %2;" : "=f"(lo), "=f"(hi) : "l"(v));
    return lo + hi;
}

__device__ __forceinline__ unsigned bar_arrive() {
    unsigned ticket;
    asm volatile("atom.release.gpu.global.add.u32 %0, [%1], %2;"
                 : "=r"(ticket) : "l"(&g_bar), "r"(1u) : "memory");
    return (ticket / GRID + 1u) * GRID;
}

__device__ __forceinline__ void bar_wait(unsigned target) {
    #pragma unroll 1
    for (int i = 0;; i++) {
        unsigned v;
        asm volatile("ld.acquire.gpu.global.u32 %0, [%1];"
                     : "=r"(v) : "l"(&g_bar) : "memory");
        if (v >= target) break;
        if (i >= 3) __nanosleep(16);
    }
}

// swizzled float4-column (64-float row stride, no padding)
__device__ __forceinline__ int swz(int r, int c) { return c ^ ((r >> 1) & 7); }

__global__ __launch_bounds__(TPB, 1)
void lowrank_fused_kernel(const float* __restrict__ x,
                          const float* __restrict__ A,
                          const float* __restrict__ Bm,
                          const float* __restrict__ bias,
                          float* __restrict__ y) {
    __shared__ __align__(16) float A_s[OTILE * 64];      // swizzled
    __shared__ float bias_s[OTILE];
    __shared__ unsigned bar1_target;
    __shared__ __align__(16) union SU {
        struct {
            float x_s[BATCH * 64];                       // plain
            float B_s[RANK * 64];                        // swizzled
        } p1;
        float T_s[BATCH * 64];                           // plain
    } u;

    const int tid = threadIdx.x;
    const int blk = blockIdx.x;
    const int k0  = blk * S1_CHUNK;
    const int o0  = blk * OTILE;

    // ---- Zero this block's 16-float slice of g_T, then ARRIVE on barrier #1
    //      immediately (warp-0 lanes 0..15 do the zeros; lane 0 arrives). ----
    if (tid < 16) {
        g_T[blk * 16 + tid] = 0.0f;
        __syncwarp(0x0000FFFFu);
        if (tid == 0) bar1_target = bar_arrive();
    }

    // ---- Tile loads ----
    {   // x[32][64] : 512 float4, plain layout
        int b = tid >> 4, c = tid & 15;
        float4 v = reinterpret_cast<const float4*>(x + b * IN_F + k0)[c];
        *reinterpret_cast<float4*>(&u.p1.x_s[b * 64 + c * 4]) = v;
    }
    #pragma unroll
    for (int i = 0; i < 2; i++) {   // B[64][64] : 1024 float4, swizzled
        int idx = tid + i * TPB;
        int r = idx >> 4, c = idx & 15;
        float4 v = reinterpret_cast<const float4*>(Bm + r * IN_F + k0)[c];
        *reinterpret_cast<float4*>(&u.p1.B_s[r * 64 + swz(r, c) * 4]) = v;
    }
    #pragma unroll
    for (int i = 0; i < 2; i++) {   // A tile [64][64] : swizzled (phase 2)
        int idx = tid + i * TPB;
        int r = idx >> 4, c = idx & 15;
        float4 v = reinterpret_cast<const float4*>(A + (o0 + r) * RANK)[c];
        *reinterpret_cast<float4*>(&A_s[r * 64 + swz(r, c) * 4]) = v;
    }
    if (tid < OTILE) bias_s[tid] = bias[o0 + tid];
    __syncthreads();

    // ---- Phase 1: thread owns r-pair (2rr, 2rr+1) x b-pair (2bp, 2bp+1) ----
    const int rr = tid & 31;        // lane id
    const int bp = tid >> 5;        // warp id -> x reads broadcast

    unsigned long long accA[2][2], accB[2][2];
    #pragma unroll
    for (int j = 0; j < 2; j++)
        #pragma unroll
        for (int i = 0; i < 2; i++) { accA[j][i] = 0ull; accB[j][i] = 0ull; }

    // First half: k4 = 0..7
    #pragma unroll
    for (int k4 = 0; k4 < 8; k4++) {
        const int bc = swz(2 * rr, k4) * 4;
        ulonglong2 bv0 = *reinterpret_cast<const ulonglong2*>(&u.p1.B_s[(2 * rr)     * 64 + bc]);
        ulonglong2 bv1 = *reinterpret_cast<const ulonglong2*>(&u.p1.B_s[(2 * rr + 1) * 64 + bc]);
        #pragma unroll
        for (int j = 0; j < 2; j++) {
            ulonglong2 xv = *reinterpret_cast<const ulonglong2*>(&u.p1.x_s[(2 * bp + j) * 64 + k4 * 4]);
            FMA2(accA[j][0], xv.x, bv0.x);
            FMA2(accB[j][0], xv.y, bv0.y);
            FMA2(accA[j][1], xv.x, bv1.x);
            FMA2(accB[j][1], xv.y, bv1.y);
        }
    }

    // Barrier #1 wait (all blocks arrived near t=0; effectively free) — REDs
    // may start only after every block's zero-stores are globally visible.
    if (tid == 0) bar_wait(bar1_target);
    __syncthreads();

    // RED wave 1: post first-half partials now so they drain through L2
    // while the second half computes.
    #pragma unroll
    for (int j = 0; j < 2; j++) {
        unsigned long long s0, s1;
        ADD2(s0, accA[j][0], accB[j][0]);
        ADD2(s1, accA[j][1], accB[j][1]);
        float f0 = hsum2(s0), f1 = hsum2(s1);
        asm volatile("red.global.add.v2.f32 [%0], {%1, %2};"
                     :: "l"(&g_T[(2 * bp + j) * RANK + 2 * rr]),
                        "f"(f0), "f"(f1) : "memory");
        accA[j][0] = 0ull; accA[j][1] = 0ull;
        accB[j][0] = 0ull; accB[j][1] = 0ull;
    }

    // Second half: k4 = 8..15
    #pragma unroll
    for (int k4 = 8; k4 < 16; k4++) {
        const int bc = swz(2 * rr, k4) * 4;
        ulonglong2 bv0 = *reinterpret_cast<const ulonglong2*>(&u.p1.B_s[(2 * rr)     * 64 + bc]);
        ulonglong2 bv1 = *reinterpret_cast<const ulonglong2*>(&u.p1.B_s[(2 * rr + 1) * 64 + bc]);
        #pragma unroll
        for (int j = 0; j < 2; j++) {
            ulonglong2 xv = *reinterpret_cast<const ulonglong2*>(&u.p1.x_s[(2 * bp + j) * 64 + k4 * 4]);
            FMA2(accA[j][0], xv.x, bv0.x);
            FMA2(accB[j][0], xv.y, bv0.y);
            FMA2(accA[j][1], xv.x, bv1.x);
            FMA2(accB[j][1], xv.y, bv1.y);
        }
    }

    // RED wave 2
    #pragma unroll
    for (int j = 0; j < 2; j++) {
        unsigned long long s0, s1;
        ADD2(s0, accA[j][0], accB[j][0]);
        ADD2(s1, accA[j][1], accB[j][1]);
        float f0 = hsum2(s0), f1 = hsum2(s1);
        asm volatile("red.global.add.v2.f32 [%0], {%1, %2};"
                     :: "l"(&g_T[(2 * bp + j) * RANK + 2 * rr]),
                        "f"(f0), "f"(f1) : "memory");
    }

    // Barrier #2: T complete.
    __syncthreads();
    if (tid == 0) bar_wait(bar_arrive());
    __syncthreads();

    // ---- Phase 2: T -> smem (plain), y = T @ A^T + bias ----
    {
        int b = tid >> 4, c = tid & 15;
        float4 v = __ldcg(reinterpret_cast<const float4*>(g_T + b * RANK) + c);
        *reinterpret_cast<float4*>(&u.T_s[b * 64 + c * 4]) = v;
    }
    __syncthreads();

    const int oo = rr;
    unsigned long long cA[2][2], cB[2][2];
    #pragma unroll
    for (int j = 0; j < 2; j++)
        #pragma unroll
        for (int i = 0; i < 2; i++) { cA[j][i] = 0ull; cB[j][i] = 0ull; }

    #pragma unroll
    for (int r4 = 0; r4 < 16; r4++) {
        const int ac = swz(2 * oo, r4) * 4;
        ulonglong2 av0 = *reinterpret_cast<const ulonglong2*>(&A_s[(2 * oo)     * 64 + ac]);
        ulonglong2 av1 = *reinterpret_cast<const ulonglong2*>(&A_s[(2 * oo + 1) * 64 + ac]);
        #pragma unroll
        for (int j = 0; j < 2; j++) {
            ulonglong2 tv = *reinterpret_cast<const ulonglong2*>(&u.T_s[(2 * bp + j) * 64 + r4 * 4]);
            FMA2(cA[j][0], tv.x, av0.x);
            FMA2(cB[j][0], tv.y, av0.y);
            FMA2(cA[j][1], tv.x, av1.x);
            FMA2(cB[j][1], tv.y, av1.y);
        }
    }

    const float2 bv2 = *reinterpret_cast<const float2*>(&bias_s[2 * oo]);
    #pragma unroll
    for (int j = 0; j < 2; j++) {
        unsigned long long s0, s1;
        ADD2(s0, cA[j][0], cB[j][0]);
        ADD2(s1, cA[j][1], cB[j][1]);
        float2 out;
        out.x = hsum2(s0) + bv2.x;
        out.y = hsum2(s1) + bv2.y;
        *reinterpret_cast<float2*>(&y[(2 * bp + j) * OUT_F + o0 + 2 * oo]) = out;
    }
}

extern "C" void kernel_launch(void* const* d_in, const int* in_sizes, int n_in,
                              void* d_out, int out_size) {
    const float* x    = (const float*)d_in[0];   // [32, 8192]
    const float* A    = (const float*)d_in[1];   // [8192, 64]
    const float* Bm   = (const float*)d_in[2];   // [64, 8192]
    const float* bias = (const float*)d_in[3];   // [8192]
    float* y = (float*)d_out;                    // [32, 8192]

    lowrank_fused_kernel<<<GRID, TPB>>>(x, A, Bm, bias, y);
}

// round 10
// speedup vs baseline: 1.4521x; 1.4521x over previous
#include <cuda_runtime.h>
#include <cuda_bf16.h>

// y = x @ (A@B)^T + bias  ==  T = x@B^T (32x64);  y = T@A^T + bias
// Fused persistent kernel: 128 blocks x 512 threads.
// - XOR-swizzled conflict-free smem tiles, 2r x 2b blocking, f32x2 FMA
// - NO global atomics: phase 1 stores per-block partials (coalesced STG),
//   each block tree-reduces a distinct 16-element slice of T from L2,
//   phase 2 consumes the reduced T. Two grid barriers total.

#define BATCH 32
#define IN_F  8192
#define OUT_F 8192
#define RANK  64
#define GRID  128
#define TPB   512
#define S1_CHUNK 64
#define OTILE    64

__device__ float        g_part[GRID][BATCH * RANK];   // 1MB partials
__device__ float        g_T[BATCH * RANK];            // reduced T
__device__ unsigned int g_bar;   // monotonic ticket counter; never reset

#define FMA2(acc, a, b) \
    asm("fma.rn.f32x2 %0, %1, %2, %0;" : "+l"(acc) : "l"(a), "l"(b))
#define ADD2(d, a, b) \
    asm("add.rn.f32x2 %0, %1, %2;" : "=l"(d) : "l"(a), "l"(b))

__device__ __forceinline__ float hsum2(unsigned long long v) {
    float lo, hi;
    asm("mov.b64 {%0, %1}, %2;" : "=f"(lo), "=f"(hi) : "l"(v));
    return lo + hi;
}

__device__ __forceinline__ unsigned bar_arrive() {
    unsigned ticket;
    asm volatile("atom.release.gpu.global.add.u32 %0, [%1], %2;"
                 : "=r"(ticket) : "l"(&g_bar), "r"(1u) : "memory");
    return (ticket / GRID + 1u) * GRID;
}

__device__ __forceinline__ void bar_wait(unsigned target) {
    #pragma unroll 1
    for (int i = 0;; i++) {
        unsigned v;
        asm volatile("ld.acquire.gpu.global.u32 %0, [%1];"
                     : "=r"(v) : "l"(&g_bar) : "memory");
        if (v >= target) break;
        if (i >= 3) __nanosleep(32);
    }
}

// swizzled float4-column (64-float row stride, no padding)
__device__ __forceinline__ int swz(int r, int c) { return c ^ ((r >> 1) & 7); }

__global__ __launch_bounds__(TPB, 1)
void lowrank_fused_kernel(const float* __restrict__ x,
                          const float* __restrict__ A,
                          const float* __restrict__ Bm,
                          const float* __restrict__ bias,
                          float* __restrict__ y) {
    __shared__ __align__(16) float A_s[OTILE * 64];      // swizzled
    __shared__ float bias_s[OTILE];
    __shared__ __align__(16) union SU {
        struct {
            float x_s[BATCH * 64];                       // plain
            float B_s[RANK * 64];                        // swizzled
        } p1;
        float T_s[BATCH * 64];                           // plain / scratch
    } u;

    const int tid = threadIdx.x;
    const int blk = blockIdx.x;
    const int k0  = blk * S1_CHUNK;
    const int o0  = blk * OTILE;

    // ---- Tile loads ----
    {   // x[32][64] : 512 float4, plain layout
        int b = tid >> 4, c = tid & 15;
        float4 v = reinterpret_cast<const float4*>(x + b * IN_F + k0)[c];
        *reinterpret_cast<float4*>(&u.p1.x_s[b * 64 + c * 4]) = v;
    }
    #pragma unroll
    for (int i = 0; i < 2; i++) {   // B[64][64] : 1024 float4, swizzled
        int idx = tid + i * TPB;
        int r = idx >> 4, c = idx & 15;
        float4 v = reinterpret_cast<const float4*>(Bm + r * IN_F + k0)[c];
        *reinterpret_cast<float4*>(&u.p1.B_s[r * 64 + swz(r, c) * 4]) = v;
    }
    #pragma unroll
    for (int i = 0; i < 2; i++) {   // A tile [64][64] : swizzled (phase 2)
        int idx = tid + i * TPB;
        int r = idx >> 4, c = idx & 15;
        float4 v = reinterpret_cast<const float4*>(A + (o0 + r) * RANK)[c];
        *reinterpret_cast<float4*>(&A_s[r * 64 + swz(r, c) * 4]) = v;
    }
    if (tid < OTILE) bias_s[tid] = bias[o0 + tid];
    __syncthreads();

    // ---- Phase 1: thread owns r-pair (2rr,2rr+1) x b-pair (2bp,2bp+1) ----
    const int rr = tid & 31;        // lane id
    const int bp = tid >> 5;        // warp id -> x reads broadcast

    unsigned long long accA[2][2], accB[2][2];
    #pragma unroll
    for (int j = 0; j < 2; j++)
        #pragma unroll
        for (int i = 0; i < 2; i++) { accA[j][i] = 0ull; accB[j][i] = 0ull; }

    #pragma unroll
    for (int k4 = 0; k4 < 16; k4++) {
        const int bc = swz(2 * rr, k4) * 4;
        ulonglong2 bv0 = *reinterpret_cast<const ulonglong2*>(&u.p1.B_s[(2 * rr)     * 64 + bc]);
        ulonglong2 bv1 = *reinterpret_cast<const ulonglong2*>(&u.p1.B_s[(2 * rr + 1) * 64 + bc]);
        #pragma unroll
        for (int j = 0; j < 2; j++) {
            ulonglong2 xv = *reinterpret_cast<const ulonglong2*>(&u.p1.x_s[(2 * bp + j) * 64 + k4 * 4]);
            FMA2(accA[j][0], xv.x, bv0.x);
            FMA2(accB[j][0], xv.y, bv0.y);
            FMA2(accA[j][1], xv.x, bv1.x);
            FMA2(accB[j][1], xv.y, bv1.y);
        }
    }

    // Store partials: coalesced STG.64, zero contention.
    #pragma unroll
    for (int j = 0; j < 2; j++) {
        unsigned long long s0, s1;
        ADD2(s0, accA[j][0], accB[j][0]);
        ADD2(s1, accA[j][1], accB[j][1]);
        float2 p; p.x = hsum2(s0); p.y = hsum2(s1);
        *reinterpret_cast<float2*>(&g_part[blk][(2 * bp + j) * RANK + 2 * rr]) = p;
    }

    // ---- Grid barrier A: all partials visible ----
    __syncthreads();
    if (tid == 0) bar_wait(bar_arrive());
    __syncthreads();

    // ---- Distributed reduce: this block owns T elements [16*blk, 16*blk+16)
    //      Warp w sums partials i = 8w..8w+7 (lanes 0..15 = elements). ----
    {
        const int w = tid >> 5, lane = tid & 31;
        if (lane < 16) {
            float racc = 0.0f;
            #pragma unroll
            for (int q = 0; q < 8; q++)
                racc += __ldcg(&g_part[w * 8 + q][blk * 16 + lane]);
            u.T_s[w * 16 + lane] = racc;   // scratch (union region free now)
        }
        __syncthreads();
        if (tid < 16) {
            float s = 0.0f;
            #pragma unroll
            for (int w2 = 0; w2 < 16; w2++) s += u.T_s[w2 * 16 + tid];
            g_T[blk * 16 + tid] = s;
        }
    }

    // ---- Grid barrier B: T complete ----
    __syncthreads();
    if (tid == 0) bar_wait(bar_arrive());
    __syncthreads();

    // ---- Phase 2: T -> smem (plain), y = T @ A^T + bias ----
    {
        int b = tid >> 4, c = tid & 15;
        float4 v = __ldcg(reinterpret_cast<const float4*>(g_T + b * RANK) + c);
        *reinterpret_cast<float4*>(&u.T_s[b * 64 + c * 4]) = v;
    }
    __syncthreads();

    const int oo = rr;
    unsigned long long cA[2][2], cB[2][2];
    #pragma unroll
    for (int j = 0; j < 2; j++)
        #pragma unroll
        for (int i = 0; i < 2; i++) { cA[j][i] = 0ull; cB[j][i] = 0ull; }

    #pragma unroll
    for (int r4 = 0; r4 < 16; r4++) {
        const int ac = swz(2 * oo, r4) * 4;
        ulonglong2 av0 = *reinterpret_cast<const ulonglong2*>(&A_s[(2 * oo)     * 64 + ac]);
        ulonglong2 av1 = *reinterpret_cast<const ulonglong2*>(&A_s[(2 * oo + 1) * 64 + ac]);
        #pragma unroll
        for (int j = 0; j < 2; j++) {
            ulonglong2 tv = *reinterpret_cast<const ulonglong2*>(&u.T_s[(2 * bp + j) * 64 + r4 * 4]);
            FMA2(cA[j][0], tv.x, av0.x);
            FMA2(cB[j][0], tv.y, av0.y);
            FMA2(cA[j][1], tv.x, av1.x);
            FMA2(cB[j][1], tv.y, av1.y);
        }
    }

    const float2 bv2 = *reinterpret_cast<const float2*>(&bias_s[2 * oo]);
    #pragma unroll
    for (int j = 0; j < 2; j++) {
        unsigned long long s0, s1;
        ADD2(s0, cA[j][0], cB[j][0]);
        ADD2(s1, cA[j][1], cB[j][1]);
        float2 out;
        out.x = hsum2(s0) + bv2.x;
        out.y = hsum2(s1) + bv2.y;
        *reinterpret_cast<float2*>(&y[(2 * bp + j) * OUT_F + o0 + 2 * oo]) = out;
    }
}

extern "C" void kernel_launch(void* const* d_in, const int* in_sizes, int n_in,
                              void* d_out, int out_size) {
    const float* x    = (const float*)d_in[0];   // [32, 8192]
    const float* A    = (const float*)d_in[1];   // [8192, 64]
    const float* Bm   = (const float*)d_in[2];   // [64, 8192]
    const float* bias = (const float*)d_in[3];   // [8192]
    float* y = (float*)d_out;                    // [32, 8192]

    lowrank_fused_kernel<<<GRID, TPB>>>(x, A, Bm, bias, y);
}

// round 11
// speedup vs baseline: 1.4849x; 1.0226x over previous
#include <cuda_runtime.h>
#include <cuda_bf16.h>

// y = x @ (A@B)^T + bias  ==  T = x@B^T (32x64);  y = T@A^T + bias
// Fused persistent kernel: 128 blocks x 512 threads.
// - XOR-swizzled conflict-free smem tiles, 2r x 2b blocking, f32x2 FMA
// - T accumulation via ONE cp.reduce.async.bulk (smem -> global, .add.f32)
//   per block; no per-thread global atomics, no tree reduce
// - barrier #1: arrive at kernel start (zeros ordered), wait just before
//   the bulk-reduce; barrier #2 after wait_group completes

#define BATCH 32
#define IN_F  8192
#define OUT_F 8192
#define RANK  64
#define GRID  128
#define TPB   512
#define S1_CHUNK 64
#define OTILE    64

__device__ __align__(16) float g_T[BATCH * RANK];
__device__ unsigned int g_bar;   // monotonic ticket counter; never reset

#define FMA2(acc, a, b) \
    asm("fma.rn.f32x2 %0, %1, %2, %0;" : "+l"(acc) : "l"(a), "l"(b))
#define ADD2(d, a, b) \
    asm("add.rn.f32x2 %0, %1, %2;" : "=l"(d) : "l"(a), "l"(b))

__device__ __forceinline__ float hsum2(unsigned long long v) {
    float lo, hi;
    asm("mov.b64 {%0, %1}, %2;" : "=f"(lo), "=f"(hi) : "l"(v));
    return lo + hi;
}

__device__ __forceinline__ unsigned bar_arrive() {
    unsigned ticket;
    asm volatile("atom.release.gpu.global.add.u32 %0, [%1], %2;"
                 : "=r"(ticket) : "l"(&g_bar), "r"(1u) : "memory");
    return (ticket / GRID + 1u) * GRID;
}

__device__ __forceinline__ void bar_wait(unsigned target) {
    #pragma unroll 1
    for (int i = 0;; i++) {
        unsigned v;
        asm volatile("ld.acquire.gpu.global.u32 %0, [%1];"
                     : "=r"(v) : "l"(&g_bar) : "memory");
        if (v >= target) break;
        if (i >= 3) __nanosleep(32);
    }
}

// swizzled float4-column (64-float row stride, no padding)
__device__ __forceinline__ int swz(int r, int c) { return c ^ ((r >> 1) & 7); }

__global__ __launch_bounds__(TPB, 1)
void lowrank_fused_kernel(const float* __restrict__ x,
                          const float* __restrict__ A,
                          const float* __restrict__ Bm,
                          const float* __restrict__ bias,
                          float* __restrict__ y) {
    __shared__ __align__(16) float A_s[OTILE * 64];      // swizzled
    __shared__ float bias_s[OTILE];
    __shared__ unsigned bar1_target;
    __shared__ __align__(16) union SU {
        struct {
            float x_s[BATCH * 64];                       // plain
            float B_s[RANK * 64];                        // swizzled
        } p1;
        float T_s[BATCH * 64];                           // partials / final T
    } u;

    const int tid = threadIdx.x;
    const int blk = blockIdx.x;
    const int k0  = blk * S1_CHUNK;
    const int o0  = blk * OTILE;

    // ---- Zero this block's 16-float slice of g_T; arrive on barrier #1
    //      immediately (warp 0, lanes 0..15 store; lane 0 arrives). ----
    if (tid < 16) {
        g_T[blk * 16 + tid] = 0.0f;
        __syncwarp(0x0000FFFFu);
        if (tid == 0) bar1_target = bar_arrive();
    }

    // ---- Tile loads ----
    {   // x[32][64] : 512 float4, plain layout
        int b = tid >> 4, c = tid & 15;
        float4 v = reinterpret_cast<const float4*>(x + b * IN_F + k0)[c];
        *reinterpret_cast<float4*>(&u.p1.x_s[b * 64 + c * 4]) = v;
    }
    #pragma unroll
    for (int i = 0; i < 2; i++) {   // B[64][64] : 1024 float4, swizzled
        int idx = tid + i * TPB;
        int r = idx >> 4, c = idx & 15;
        float4 v = reinterpret_cast<const float4*>(Bm + r * IN_F + k0)[c];
        *reinterpret_cast<float4*>(&u.p1.B_s[r * 64 + swz(r, c) * 4]) = v;
    }
    #pragma unroll
    for (int i = 0; i < 2; i++) {   // A tile [64][64] : swizzled (phase 2)
        int idx = tid + i * TPB;
        int r = idx >> 4, c = idx & 15;
        float4 v = reinterpret_cast<const float4*>(A + (o0 + r) * RANK)[c];
        *reinterpret_cast<float4*>(&A_s[r * 64 + swz(r, c) * 4]) = v;
    }
    if (tid < OTILE) bias_s[tid] = bias[o0 + tid];
    __syncthreads();

    // ---- Phase 1: thread owns r-pair (2rr,2rr+1) x b-pair (2bp,2bp+1) ----
    const int rr = tid & 31;        // lane id
    const int bp = tid >> 5;        // warp id -> x reads broadcast

    unsigned long long accA[2][2], accB[2][2];
    #pragma unroll
    for (int j = 0; j < 2; j++)
        #pragma unroll
        for (int i = 0; i < 2; i++) { accA[j][i] = 0ull; accB[j][i] = 0ull; }

    #pragma unroll
    for (int k4 = 0; k4 < 16; k4++) {
        const int bc = swz(2 * rr, k4) * 4;
        ulonglong2 bv0 = *reinterpret_cast<const ulonglong2*>(&u.p1.B_s[(2 * rr)     * 64 + bc]);
        ulonglong2 bv1 = *reinterpret_cast<const ulonglong2*>(&u.p1.B_s[(2 * rr + 1) * 64 + bc]);
        #pragma unroll
        for (int j = 0; j < 2; j++) {
            ulonglong2 xv = *reinterpret_cast<const ulonglong2*>(&u.p1.x_s[(2 * bp + j) * 64 + k4 * 4]);
            FMA2(accA[j][0], xv.x, bv0.x);
            FMA2(accB[j][0], xv.y, bv0.y);
            FMA2(accA[j][1], xv.x, bv1.x);
            FMA2(accB[j][1], xv.y, bv1.y);
        }
    }

    // ---- Partials -> smem (T_s overlaps the now-dead x_s/B_s region) ----
    __syncthreads();   // everyone done reading x_s/B_s
    #pragma unroll
    for (int j = 0; j < 2; j++) {
        unsigned long long s0, s1;
        ADD2(s0, accA[j][0], accB[j][0]);
        ADD2(s1, accA[j][1], accB[j][1]);
        float2 p; p.x = hsum2(s0); p.y = hsum2(s1);
        *reinterpret_cast<float2*>(&u.T_s[(2 * bp + j) * 64 + 2 * rr]) = p;
    }
    __syncthreads();   // partial tile complete in smem

    // ---- One bulk async reduce: smem T_s (8KB) +=> g_T ----
    if (tid == 0) {
        bar_wait(bar1_target);   // all blocks' zero-stores globally visible
        unsigned smem_addr;
        asm("{ .reg .u64 t; cvta.to.shared.u64 t, %1; cvt.u32.u64 %0, t; }"
            : "=r"(smem_addr) : "l"((void*)u.T_s));
        asm volatile("fence.proxy.async.shared::cta;" ::: "memory");
        asm volatile(
            "cp.reduce.async.bulk.global.shared::cta.bulk_group.add.f32 "
            "[%0], [%1], %2;"
            :: "l"(g_T), "r"(smem_addr), "r"((unsigned)(BATCH * RANK * 4))
            : "memory");
        asm volatile("cp.async.bulk.commit_group;" ::: "memory");
        asm volatile("cp.async.bulk.wait_group 0;" ::: "memory");
        // Barrier #2: all blocks' bulk reduces complete -> T final.
        bar_wait(bar_arrive());
    }
    __syncthreads();

    // ---- Phase 2: final T -> smem (plain), y = T @ A^T + bias ----
    {
        int b = tid >> 4, c = tid & 15;
        float4 v = __ldcg(reinterpret_cast<const float4*>(g_T + b * RANK) + c);
        *reinterpret_cast<float4*>(&u.T_s[b * 64 + c * 4]) = v;
    }
    __syncthreads();

    const int oo = rr;
    unsigned long long cA[2][2], cB[2][2];
    #pragma unroll
    for (int j = 0; j < 2; j++)
        #pragma unroll
        for (int i = 0; i < 2; i++) { cA[j][i] = 0ull; cB[j][i] = 0ull; }

    #pragma unroll
    for (int r4 = 0; r4 < 16; r4++) {
        const int ac = swz(2 * oo, r4) * 4;
        ulonglong2 av0 = *reinterpret_cast<const ulonglong2*>(&A_s[(2 * oo)     * 64 + ac]);
        ulonglong2 av1 = *reinterpret_cast<const ulonglong2*>(&A_s[(2 * oo + 1) * 64 + ac]);
        #pragma unroll
        for (int j = 0; j < 2; j++) {
            ulonglong2 tv = *reinterpret_cast<const ulonglong2*>(&u.T_s[(2 * bp + j) * 64 + r4 * 4]);
            FMA2(cA[j][0], tv.x, av0.x);
            FMA2(cB[j][0], tv.y, av0.y);
            FMA2(cA[j][1], tv.x, av1.x);
            FMA2(cB[j][1], tv.y, av1.y);
        }
    }

    const float2 bv2 = *reinterpret_cast<const float2*>(&bias_s[2 * oo]);
    #pragma unroll
    for (int j = 0; j < 2; j++) {
        unsigned long long s0, s1;
        ADD2(s0, cA[j][0], cB[j][0]);
        ADD2(s1, cA[j][1], cB[j][1]);
        float2 out;
        out.x = hsum2(s0) + bv2.x;
        out.y = hsum2(s1) + bv2.y;
        *reinterpret_cast<float2*>(&y[(2 * bp + j) * OUT_F + o0 + 2 * oo]) = out;
    }
}

extern "C" void kernel_launch(void* const* d_in, const int* in_sizes, int n_in,
                              void* d_out, int out_size) {
    const float* x    = (const float*)d_in[0];   // [32, 8192]
    const float* A    = (const float*)d_in[1];   // [8192, 64]
    const float* Bm   = (const float*)d_in[2];   // [64, 8192]
    const float* bias = (const float*)d_in[3];   // [8192]
    float* y = (float*)d_out;                    // [32, 8192]

    lowrank_fused_kernel<<<GRID, TPB>>>(x, A, Bm, bias, y);
}

// round 12
// speedup vs baseline: 1.7642x; 1.1881x over previous
#include <cuda_runtime.h>
#include <cuda_bf16.h>

// y = x @ (A@B)^T + bias  ==  T = x@B^T (32x64);  y = T@A^T + bias
// Fused persistent kernel: 128 blocks x 256 threads.
// - XOR-swizzled conflict-free smem tiles (proven R7 pattern)
// - 2r x 4b register blocking (halves B_s/A_s crossbar traffic vs 2rx2b)
// - single-wave red.global.add.v2.f32 accumulation (proven best)
// - grid barrier #1 split (arrive post-load / wait post-compute), #2 standard

#define BATCH 32
#define IN_F  8192
#define OUT_F 8192
#define RANK  64
#define GRID  128
#define TPB   256
#define S1_CHUNK 64
#define OTILE    64

__device__ float        g_T[BATCH * RANK];
__device__ unsigned int g_bar;   // monotonic ticket counter; never reset

#define FMA2(acc, a, b) \
    asm("fma.rn.f32x2 %0, %1, %2, %0;" : "+l"(acc) : "l"(a), "l"(b))
#define ADD2(d, a, b) \
    asm("add.rn.f32x2 %0, %1, %2;" : "=l"(d) : "l"(a), "l"(b))

__device__ __forceinline__ float hsum2(unsigned long long v) {
    float lo, hi;
    asm("mov.b64 {%0, %1}, %2;" : "=f"(lo), "=f"(hi) : "l"(v));
    return lo + hi;
}

__device__ __forceinline__ unsigned bar_arrive() {
    unsigned ticket;
    asm volatile("atom.release.gpu.global.add.u32 %0, [%1], %2;"
                 : "=r"(ticket) : "l"(&g_bar), "r"(1u) : "memory");
    return (ticket / GRID + 1u) * GRID;
}

__device__ __forceinline__ void bar_wait(unsigned target) {
    #pragma unroll 1
    for (int i = 0;; i++) {
        unsigned v;
        asm volatile("ld.acquire.gpu.global.u32 %0, [%1];"
                     : "=r"(v) : "l"(&g_bar) : "memory");
        if (v >= target) break;
        if (i >= 3) __nanosleep(32);
    }
}

// swizzled float4-column (64-float row stride, no padding)
__device__ __forceinline__ int swz(int r, int c) { return c ^ ((r >> 1) & 7); }

__global__ __launch_bounds__(TPB, 1)
void lowrank_fused_kernel(const float* __restrict__ x,
                          const float* __restrict__ A,
                          const float* __restrict__ Bm,
                          const float* __restrict__ bias,
                          float* __restrict__ y) {
    __shared__ __align__(16) float A_s[OTILE * 64];      // swizzled
    __shared__ float bias_s[OTILE];
    __shared__ unsigned bar1_target;
    __shared__ __align__(16) union SU {
        struct {
            float x_s[BATCH * 64];                       // plain
            float B_s[RANK * 64];                        // swizzled
        } p1;
        float T_s[BATCH * 64];                           // plain
    } u;

    const int tid = threadIdx.x;
    const int blk = blockIdx.x;
    const int k0  = blk * S1_CHUNK;
    const int o0  = blk * OTILE;

    // ---- Zero this block's 16-float slice of g_T ----
    if (tid < 16) g_T[blk * 16 + tid] = 0.0f;

    // ---- Tile loads (256 threads) ----
    #pragma unroll
    for (int i = 0; i < 2; i++) {   // x[32][64] : 512 float4, plain
        int idx = tid + i * TPB;
        int b = idx >> 4, c = idx & 15;
        float4 v = reinterpret_cast<const float4*>(x + b * IN_F + k0)[c];
        *reinterpret_cast<float4*>(&u.p1.x_s[b * 64 + c * 4]) = v;
    }
    #pragma unroll
    for (int i = 0; i < 4; i++) {   // B[64][64] : 1024 float4, swizzled
        int idx = tid + i * TPB;
        int r = idx >> 4, c = idx & 15;
        float4 v = reinterpret_cast<const float4*>(Bm + r * IN_F + k0)[c];
        *reinterpret_cast<float4*>(&u.p1.B_s[r * 64 + swz(r, c) * 4]) = v;
    }
    #pragma unroll
    for (int i = 0; i < 4; i++) {   // A tile [64][64] : swizzled (phase 2)
        int idx = tid + i * TPB;
        int r = idx >> 4, c = idx & 15;
        float4 v = reinterpret_cast<const float4*>(A + (o0 + r) * RANK)[c];
        *reinterpret_cast<float4*>(&A_s[r * 64 + swz(r, c) * 4]) = v;
    }
    if (tid < OTILE) bias_s[tid] = bias[o0 + tid];
    __syncthreads();

    // Barrier #1 ARRIVE (early): orders all blocks' zero-stores.
    if (tid == 0) bar1_target = bar_arrive();

    // ---- Phase 1: thread owns r-pair (2rr,2rr+1) x b-quad (4bq..4bq+3) ----
    const int rr = tid & 31;        // lane id -> proven conflict-free B reads
    const int bq = tid >> 5;        // warp id (0..7) -> x reads broadcast
    const int b0 = bq * 4;

    unsigned long long accA[4][2], accB[4][2];
    #pragma unroll
    for (int j = 0; j < 4; j++)
        #pragma unroll
        for (int i = 0; i < 2; i++) { accA[j][i] = 0ull; accB[j][i] = 0ull; }

    #pragma unroll
    for (int k4 = 0; k4 < 16; k4++) {
        const int bc = swz(2 * rr, k4) * 4;
        ulonglong2 bv0 = *reinterpret_cast<const ulonglong2*>(&u.p1.B_s[(2 * rr)     * 64 + bc]);
        ulonglong2 bv1 = *reinterpret_cast<const ulonglong2*>(&u.p1.B_s[(2 * rr + 1) * 64 + bc]);
        #pragma unroll
        for (int j = 0; j < 4; j++) {
            ulonglong2 xv = *reinterpret_cast<const ulonglong2*>(&u.p1.x_s[(b0 + j) * 64 + k4 * 4]);
            FMA2(accA[j][0], xv.x, bv0.x);
            FMA2(accB[j][0], xv.y, bv0.y);
            FMA2(accA[j][1], xv.x, bv1.x);
            FMA2(accB[j][1], xv.y, bv1.y);
        }
    }

    // Barrier #1 WAIT (late): hidden under phase-1 compute.
    if (tid == 0) bar_wait(bar1_target);
    __syncthreads();

    // Single-wave vector REDs (adjacent r -> v2); proven best reduction.
    #pragma unroll
    for (int j = 0; j < 4; j++) {
        unsigned long long s0, s1;
        ADD2(s0, accA[j][0], accB[j][0]);
        ADD2(s1, accA[j][1], accB[j][1]);
        float f0 = hsum2(s0), f1 = hsum2(s1);
        asm volatile("red.global.add.v2.f32 [%0], {%1, %2};"
                     :: "l"(&g_T[(b0 + j) * RANK + 2 * rr]),
                        "f"(f0), "f"(f1) : "memory");
    }

    // Barrier #2: T complete.
    __syncthreads();
    if (tid == 0) bar_wait(bar_arrive());
    __syncthreads();

    // ---- Phase 2: T -> smem (plain), y = T @ A^T + bias ----
    #pragma unroll
    for (int i = 0; i < 2; i++) {
        int idx = tid + i * TPB;
        int b = idx >> 4, c = idx & 15;
        float4 v = __ldcg(reinterpret_cast<const float4*>(g_T + b * RANK) + c);
        *reinterpret_cast<float4*>(&u.T_s[b * 64 + c * 4]) = v;
    }
    __syncthreads();

    const int oo = rr;              // o-pair index = lane id
    unsigned long long cA[4][2], cB[4][2];
    #pragma unroll
    for (int j = 0; j < 4; j++)
        #pragma unroll
        for (int i = 0; i < 2; i++) { cA[j][i] = 0ull; cB[j][i] = 0ull; }

    #pragma unroll
    for (int r4 = 0; r4 < 16; r4++) {
        const int ac = swz(2 * oo, r4) * 4;
        ulonglong2 av0 = *reinterpret_cast<const ulonglong2*>(&A_s[(2 * oo)     * 64 + ac]);
        ulonglong2 av1 = *reinterpret_cast<const ulonglong2*>(&A_s[(2 * oo + 1) * 64 + ac]);
        #pragma unroll
        for (int j = 0; j < 4; j++) {
            ulonglong2 tv = *reinterpret_cast<const ulonglong2*>(&u.T_s[(b0 + j) * 64 + r4 * 4]);
            FMA2(cA[j][0], tv.x, av0.x);
            FMA2(cB[j][0], tv.y, av0.y);
            FMA2(cA[j][1], tv.x, av1.x);
            FMA2(cB[j][1], tv.y, av1.y);
        }
    }

    const float2 bv2 = *reinterpret_cast<const float2*>(&bias_s[2 * oo]);
    #pragma unroll
    for (int j = 0; j < 4; j++) {
        unsigned long long s0, s1;
        ADD2(s0, cA[j][0], cB[j][0]);
        ADD2(s1, cA[j][1], cB[j][1]);
        float2 out;
        out.x = hsum2(s0) + bv2.x;
        out.y = hsum2(s1) + bv2.y;
        *reinterpret_cast<float2*>(&y[(b0 + j) * OUT_F + o0 + 2 * oo]) = out;
    }
}

extern "C" void kernel_launch(void* const* d_in, const int* in_sizes, int n_in,
                              void* d_out, int out_size) {
    const float* x    = (const float*)d_in[0];   // [32, 8192]
    const float* A    = (const float*)d_in[1];   // [8192, 64]
    const float* Bm   = (const float*)d_in[2];   // [64, 8192]
    const float* bias = (const float*)d_in[3];   // [8192]
    float* y = (float*)d_out;                    // [32, 8192]

    lowrank_fused_kernel<<<GRID, TPB>>>(x, A, Bm, bias, y);
}